// round 9
// baseline (speedup 1.0000x reference)
#include <cuda_runtime.h>

#define T_LEN  1024
#define NSTEP  1023
#define B_SZ   8192

typedef unsigned long long ull;

// scratch: time-major inputs + c_t buffer
__device__ int   g_act_t[T_LEN * B_SZ];            // [t][b]
__device__ float g_rew_t[T_LEN * B_SZ];            // [t][b]
__device__ float g_c[(size_t)B_SZ * NSTEP * 4];    // [b][t][4]

// ---------------- packed f32x2 helpers ----------------
__device__ __forceinline__ void ffma2(ull& d, ull a, ull b) {
    asm("fma.rn.f32x2 %0, %1, %2, %0;" : "+l"(d) : "l"(a), "l"(b));
}
__device__ __forceinline__ ull mul2(ull a, ull b) {
    ull r; asm("mul.rn.f32x2 %0, %1, %2;" : "=l"(r) : "l"(a), "l"(b)); return r;
}
__device__ __forceinline__ ull add2(ull a, ull b) {
    ull r; asm("add.rn.f32x2 %0, %1, %2;" : "=l"(r) : "l"(a), "l"(b)); return r;
}
__device__ __forceinline__ ull pack2(float x, float y) {
    ull r; asm("mov.b64 %0, {%1, %2};" : "=l"(r) : "f"(x), "f"(y)); return r;
}
__device__ __forceinline__ float2 unpack2(ull v) {
    float2 r; asm("mov.b64 {%0, %1}, %2;" : "=f"(r.x), "=f"(r.y) : "l"(v)); return r;
}
__device__ __forceinline__ ull shflx64(ull v, int m) {
    return __shfl_xor_sync(0xFFFFFFFFu, v, m);
}
// input pre-scaled by 2*log2(e): tanh = 1 - 2/(2^x' + 1)   (~1e-6 abs err)
__device__ __forceinline__ float tanh_pre(float xs) {
    float e, r;
    asm("ex2.approx.f32 %0, %1;" : "=f"(e) : "f"(xs));
    asm("rcp.approx.f32 %0, %1;" : "=f"(r) : "f"(e + 1.0f));
    return fmaf(-2.0f, r, 1.0f);
}
#define TANH_SC 2.8853900817779268f   // 2*log2(e)

// ---------------- transpose [B][T] -> [T][B] ----------------
__global__ void __launch_bounds__(256)
transpose_kernel(const int* __restrict__ act, const float* __restrict__ rew) {
    __shared__ unsigned tile[32][33];
    const int tt = blockIdx.x * 32, tb = blockIdx.y * 32;
    const unsigned* src = (blockIdx.z == 0) ? (const unsigned*)act : (const unsigned*)rew;
    unsigned*       dst = (blockIdx.z == 0) ? (unsigned*)g_act_t  : (unsigned*)g_rew_t;
    const int tx = threadIdx.x, ty = threadIdx.y;
    #pragma unroll
    for (int i = 0; i < 32; i += 8)
        tile[ty + i][tx] = src[(long long)(tb + ty + i) * T_LEN + tt + tx];
    __syncthreads();
    #pragma unroll
    for (int i = 0; i < 32; i += 8)
        dst[(long long)(tt + ty + i) * B_SZ + tb + tx] = tile[tx][ty + i];
}

// ---------------- main recurrent kernel ----------------
// grid = 256 CTAs x 256 thr (8 warps -> wid%4 spreads over all 4 SMSPs).
// CTAs 0..127: reward module; 128..255: action module. Each warp owns 8
// elements; 4 lanes/element (lane ll handles rows/dims [8ll,8ll+8)). State is
// double-buffered in SMEM per element; matvec streams state via broadcast
// LDS.128; each lane writes its 8 new dims (2 STS.128); one __syncwarp/step.
// 2048 warps chip-wide -> 4 warps per SMSP on fully-loaded SMs.
__global__ void __launch_bounds__(256, 2)
memann_mod(const float* __restrict__ w_r1, const float* __restrict__ b_r1,
           const float* __restrict__ w_r2, const float* __restrict__ b_r2,
           const float* __restrict__ w_a1, const float* __restrict__ b_a1,
           const float* __restrict__ w_a2, const float* __restrict__ b_a2,
           float*       __restrict__ out)
{
    // weights: [ll][r*16 + p] (row = 8ll + r, p = x-pair) — prescaled.
    // ll-stride 130 ull = 1040B -> lane addresses 16B apart mod 128: conflict-free.
    __shared__ __align__(16) ull w1s[4][130];
    // action one-hot column + bias (prescaled): [a][ll][rp] = {row, row+1}
    __shared__ __align__(16) ull colba[4][4][4];
    // state, double buffered: [warp][parity][element][pair]; elem stride 18 ull
    // = 144B -> the 8 element addresses hit distinct 16B quads (conflict-free).
    __shared__ __align__(16) ull st[8][2][8][18];

    const int tid = threadIdx.x;
    const bool is_rew = blockIdx.x < 128;

    // ---- one-time staging ----
    if (is_rew) {
        for (int i = tid; i < 512; i += 256) {
            const int ll = i >> 7, r = (i >> 4) & 7, p = i & 15;
            const int row = 8 * ll + r;
            w1s[ll][r * 16 + p] = pack2(w_r1[row * 33 + 1 + 2 * p] * TANH_SC,
                                        w_r1[row * 33 + 2 + 2 * p] * TANH_SC);
        }
    } else {
        for (int i = tid; i < 512; i += 256) {
            const int ll = i >> 7, r = (i >> 4) & 7, p = i & 15;
            const int row = 8 * ll + r;
            w1s[ll][r * 16 + p] = pack2(w_a1[row * 36 + 4 + 2 * p] * TANH_SC,
                                        w_a1[row * 36 + 5 + 2 * p] * TANH_SC);
        }
        if (tid < 64) {
            const int a = tid >> 4, ll = (tid >> 2) & 3, rp = tid & 3;
            const int row = 8 * ll + 2 * rp;
            colba[a][ll][rp] =
                pack2((w_a1[row * 36 + a] + b_a1[row]) * TANH_SC,
                      (w_a1[(row + 1) * 36 + a] + b_a1[row + 1]) * TANH_SC);
        }
    }
    for (int i = tid; i < 8 * 2 * 8 * 18; i += 256) (&st[0][0][0][0])[i] = 0ull;
    __syncthreads();

    const int lane = tid & 31, wid = tid >> 5;
    const int e  = lane >> 2;          // element within warp
    const int ll = lane & 3;           // sub-lane: rows/dims [8ll, 8ll+8)
    const long long b =
        (long long)(is_rew ? blockIdx.x : blockIdx.x - 128) * 64 + wid * 8 + e;
    const int*   ap  = g_act_t + b;
    const float* rp_ = g_rew_t + b;
    ull (*stw)[8][18] = &st[wid][0];   // this warp's [parity][e][pair]

    if (is_rew) {
        // ---------------- reward module ----------------
        ull bw[8], w2s[4];
        #pragma unroll
        for (int r = 0; r < 8; r++) {
            const int row = 8 * ll + r;
            bw[r] = pack2(b_r1[row] * TANH_SC, w_r1[row * 33] * TANH_SC);
        }
        #pragma unroll
        for (int u = 0; u < 4; u++)
            w2s[u] = pack2(w_r2[8 * ll + 2 * u], w_r2[8 * ll + 2 * u + 1]);
        const float br2 = b_r2[0];
        float q = 0.0f;
        float* op = out + ((size_t)b * NSTEP) * 4 + ll;

        int   a_cur = ap[0];
        float r_cur = rp_[0];
        for (int t = 0; t < NSTEP; t++) {
            const int   a_nxt = ap[(t + 1) * B_SZ];
            const float r_nxt = rp_[(t + 1) * B_SZ];

            const ull rv = pack2(1.0f, r_cur);
            ull acc[8];
            #pragma unroll
            for (int r = 0; r < 8; r++) acc[r] = mul2(bw[r], rv);  // {b', w0'*r}

            const ull* sb = &stw[t & 1][e][0];
            #pragma unroll
            for (int pp = 0; pp < 8; pp++) {
                const ulonglong2 sv = *(const ulonglong2*)&sb[2 * pp];
                #pragma unroll
                for (int r = 0; r < 8; r++) {
                    const ulonglong2 w = *(const ulonglong2*)&w1s[ll][r * 16 + 2 * pp];
                    ffma2(acc[r], w.x, sv.x);
                    ffma2(acc[r], w.y, sv.y);
                }
            }
            float sn[8];
            #pragma unroll
            for (int r = 0; r < 8; r++) {
                const float2 u = unpack2(acc[r]);
                sn[r] = tanh_pre(u.x + u.y);
            }
            ull sp[4];
            #pragma unroll
            for (int u = 0; u < 4; u++) sp[u] = pack2(sn[2 * u], sn[2 * u + 1]);

            ull* wb = &stw[(t + 1) & 1][e][0];
            *(ulonglong2*)&wb[4 * ll]     = make_ulonglong2(sp[0], sp[1]);
            *(ulonglong2*)&wb[4 * ll + 2] = make_ulonglong2(sp[2], sp[3]);
            __syncwarp();

            // q_new = w_r2 . s + b_r2 : own-8-dims partial + 4-lane reduce
            ull qa = 0ull;
            #pragma unroll
            for (int u = 0; u < 4; u++) ffma2(qa, w2s[u], sp[u]);
            const float2 qf = unpack2(qa);
            float qs = qf.x + qf.y;
            qs += __shfl_xor_sync(0xFFFFFFFFu, qs, 1);
            qs += __shfl_xor_sync(0xFFFFFFFFu, qs, 2);
            const float q_new = qs + br2;

            q = (a_cur == ll) ? q_new : q * 0.95f;
            op[(size_t)t * 4] = q;

            a_cur = a_nxt; r_cur = r_nxt;
        }
    } else {
        // ---------------- action-history module ----------------
        ull w2a[4][4];
        #pragma unroll
        for (int k = 0; k < 4; k++)
            #pragma unroll
            for (int u = 0; u < 4; u++)
                w2a[k][u] = pack2(w_a2[k * 32 + 8 * ll + 2 * u],
                                  w_a2[k * 32 + 8 * ll + 2 * u + 1]);
        const float ba = b_a2[ll];
        float* cp = g_c + ((size_t)b * NSTEP) * 4 + ll;

        int a_cur = ap[0];
        for (int t = 0; t < NSTEP; t++) {
            const int a_nxt = ap[(t + 1) * B_SZ];

            ull acc[8];
            #pragma unroll
            for (int r = 0; r < 8; r++) acc[r] = 0ull;

            const ull* sb = &stw[t & 1][e][0];
            #pragma unroll
            for (int pp = 0; pp < 8; pp++) {
                const ulonglong2 sv = *(const ulonglong2*)&sb[2 * pp];
                #pragma unroll
                for (int r = 0; r < 8; r++) {
                    const ulonglong2 w = *(const ulonglong2*)&w1s[ll][r * 16 + 2 * pp];
                    ffma2(acc[r], w.x, sv.x);
                    ffma2(acc[r], w.y, sv.y);
                }
            }
            const ulonglong2 cbA = *(const ulonglong2*)&colba[a_cur][ll][0];
            const ulonglong2 cbB = *(const ulonglong2*)&colba[a_cur][ll][2];
            const float2 c0f = unpack2(cbA.x), c1f = unpack2(cbA.y);
            const float2 c2f = unpack2(cbB.x), c3f = unpack2(cbB.y);
            const float cbv[8] = {c0f.x, c0f.y, c1f.x, c1f.y,
                                  c2f.x, c2f.y, c3f.x, c3f.y};

            float sn[8];
            #pragma unroll
            for (int r = 0; r < 8; r++) {
                const float2 u = unpack2(acc[r]);
                sn[r] = tanh_pre(u.x + u.y + cbv[r]);
            }
            ull sp[4];
            #pragma unroll
            for (int u = 0; u < 4; u++) sp[u] = pack2(sn[2 * u], sn[2 * u + 1]);

            ull* wb = &stw[(t + 1) & 1][e][0];
            *(ulonglong2*)&wb[4 * ll]     = make_ulonglong2(sp[0], sp[1]);
            *(ulonglong2*)&wb[4 * ll + 2] = make_ulonglong2(sp[2], sp[3]);
            __syncwarp();

            // c_k partials over own 8 dims, packed 4-lane reduce
            ull ca0 = 0ull, ca1 = 0ull, ca2 = 0ull, ca3 = 0ull;
            #pragma unroll
            for (int u = 0; u < 4; u++) {
                ffma2(ca0, w2a[0][u], sp[u]);
                ffma2(ca1, w2a[1][u], sp[u]);
                ffma2(ca2, w2a[2][u], sp[u]);
                ffma2(ca3, w2a[3][u], sp[u]);
            }
            const float2 f0 = unpack2(ca0), f1 = unpack2(ca1);
            const float2 f2 = unpack2(ca2), f3 = unpack2(ca3);
            ull v01 = pack2(f0.x + f0.y, f1.x + f1.y);
            ull v23 = pack2(f2.x + f2.y, f3.x + f3.y);
            v01 = add2(v01, shflx64(v01, 1));
            v23 = add2(v23, shflx64(v23, 1));
            v01 = add2(v01, shflx64(v01, 2));
            v23 = add2(v23, shflx64(v23, 2));
            const ull    vsel = (ll & 2) ? v23 : v01;
            const float2 vv   = unpack2(vsel);
            cp[(size_t)t * 4] = ((ll & 1) ? vv.y : vv.x) + ba;

            a_cur = a_nxt;
        }
    }
}

// ---------------- out += c ----------------
__global__ void __launch_bounds__(256)
add_kernel(float* __restrict__ out) {
    const size_t n4 = (size_t)B_SZ * NSTEP;
    float4* o = (float4*)out;
    const float4* c = (const float4*)g_c;
    for (size_t i = (size_t)blockIdx.x * 256 + threadIdx.x; i < n4;
         i += (size_t)gridDim.x * 256) {
        float4 a = o[i], b = c[i];
        a.x += b.x; a.y += b.y; a.z += b.z; a.w += b.w;
        o[i] = a;
    }
}

extern "C" void kernel_launch(void* const* d_in, const int* in_sizes, int n_in,
                              void* d_out, int out_size) {
    (void)in_sizes; (void)n_in; (void)out_size;
    transpose_kernel<<<dim3(T_LEN / 32, B_SZ / 32, 2), dim3(32, 8)>>>(
        (const int*)d_in[0], (const float*)d_in[1]);
    memann_mod<<<256, 256>>>(
        (const float*)d_in[2], (const float*)d_in[3],
        (const float*)d_in[4], (const float*)d_in[5],
        (const float*)d_in[6], (const float*)d_in[7],
        (const float*)d_in[8], (const float*)d_in[9],
        (float*)d_out);
    add_kernel<<<2048, 256>>>((float*)d_out);
}

// round 10
// speedup vs baseline: 1.7687x; 1.7687x over previous
#include <cuda_runtime.h>

#define T_LEN  1024
#define NSTEP  1023
#define B_SZ   8192

typedef unsigned long long ull;

// scratch: time-major inputs
__device__ int   g_act_t[T_LEN * B_SZ];            // [t][b]
__device__ float g_rew_t[T_LEN * B_SZ];            // [t][b]

// ---------------- packed f32x2 helpers ----------------
__device__ __forceinline__ void ffma2(ull& d, ull a, ull b) {
    asm("fma.rn.f32x2 %0, %1, %2, %0;" : "+l"(d) : "l"(a), "l"(b));
}
__device__ __forceinline__ ull mul2(ull a, ull b) {
    ull r; asm("mul.rn.f32x2 %0, %1, %2;" : "=l"(r) : "l"(a), "l"(b)); return r;
}
__device__ __forceinline__ ull add2(ull a, ull b) {
    ull r; asm("add.rn.f32x2 %0, %1, %2;" : "=l"(r) : "l"(a), "l"(b)); return r;
}
__device__ __forceinline__ ull pack2(float x, float y) {
    ull r; asm("mov.b64 %0, {%1, %2};" : "=l"(r) : "f"(x), "f"(y)); return r;
}
__device__ __forceinline__ float2 unpack2(ull v) {
    float2 r; asm("mov.b64 {%0, %1}, %2;" : "=f"(r.x), "=f"(r.y) : "l"(v)); return r;
}
__device__ __forceinline__ ull shflx64(ull v, int m) {
    return __shfl_xor_sync(0xFFFFFFFFu, v, m);
}
// input pre-scaled by 2*log2(e):  tanh = 1 - 2/(2^x' + 1)   (~1e-6 abs err)
__device__ __forceinline__ float tanh_pre(float xs) {
    float e, r;
    asm("ex2.approx.f32 %0, %1;" : "=f"(e) : "f"(xs));
    asm("rcp.approx.f32 %0, %1;" : "=f"(r) : "f"(e + 1.0f));
    return fmaf(-2.0f, r, 1.0f);
}
#define TANH_SC 2.8853900817779268f   // 2*log2(e)

// ---------------- transpose [B][T] -> [T][B]  +  zero(out) ----------------
// grid = (32, 256, 3): z=0 transposes actions, z=1 rewards, z=2 zeroes out.
__global__ void __launch_bounds__(256)
transpose_kernel(const int* __restrict__ act, const float* __restrict__ rew,
                 float* __restrict__ out) {
    const int tx = threadIdx.x, ty = threadIdx.y;
    if (blockIdx.z == 2) {
        // zero the output buffer: 8192 blocks x 1023 float4 each
        const size_t base =
            ((size_t)blockIdx.y * gridDim.x + blockIdx.x) * (size_t)NSTEP;
        float4* o4 = (float4*)out;
        const float4 z = make_float4(0.f, 0.f, 0.f, 0.f);
        const int tid = ty * 32 + tx;
        for (int i = tid; i < NSTEP; i += 256) o4[base + i] = z;
        return;
    }
    __shared__ unsigned tile[32][33];
    const int tt = blockIdx.x * 32, tb = blockIdx.y * 32;
    const unsigned* src = (blockIdx.z == 0) ? (const unsigned*)act : (const unsigned*)rew;
    unsigned*       dst = (blockIdx.z == 0) ? (unsigned*)g_act_t  : (unsigned*)g_rew_t;
    #pragma unroll
    for (int i = 0; i < 32; i += 8)
        tile[ty + i][tx] = src[(long long)(tb + ty + i) * T_LEN + tt + tx];
    __syncthreads();
    #pragma unroll
    for (int i = 0; i < 32; i += 8)
        dst[(long long)(tt + ty + i) * B_SZ + tb + tx] = tile[tx][ty + i];
}

// ---------------- main recurrent kernel (R3 geometry, prescaled, RED out) ----
// grid = 128 CTAs x 256 thr (8 warps). CTAs 0..63: reward module; 64..127: action.
// Warp handles 16 elements; lane pair (2e, 2e+1) shares element e: lane h owns
// weight rows / state dims [16h, 16h+16) in registers; halves swap via SHFL.
// Both modules atomicAdd (REDG) their contribution into the zeroed out buffer:
// out[b][t][k] = q_k + c_k, order-independent (fp add is commutative vs 0).
__global__ void __launch_bounds__(256, 1)
memann_mod(const float* __restrict__ w_r1, const float* __restrict__ b_r1,
           const float* __restrict__ w_r2, const float* __restrict__ b_r2,
           const float* __restrict__ w_a1, const float* __restrict__ b_a1,
           const float* __restrict__ w_a2, const float* __restrict__ b_a2,
           float*       __restrict__ out)
{
    // weight SMEM, interleaved so the 2 per-warp addresses are 16B apart
    __shared__ __align__(16) ulonglong2 wrk[16][8][2];  // [m][pp][h]: row h*16+m
    __shared__ __align__(16) ulonglong2 wak[16][8][2];
    __shared__ __align__(16) ull  bw1s[16][2];          // {b_r1', w_r1[.,0]'}
    __shared__ __align__(16) ull  wr2s[2][8];
    __shared__ __align__(16) ull  wa2s[4][2][8];
    __shared__ __align__(16) float colbf[4][2][16];     // (w_a1[r][a]+b_a1[r])'
    __shared__ float sc[5];                              // b_r2, b_a2[0..3]

    const int tid = threadIdx.x;
    const bool is_reward = blockIdx.x < 64;

    // ---- staging ----
    if (is_reward) {
        #pragma unroll
        for (int k = 0; k < 2; k++) {
            int idx = tid * 2 + k;                 // 512 ull
            int u2 = idx & 1, h = (idx >> 1) & 1, pp = (idx >> 2) & 7, m = idx >> 5;
            int row = h * 16 + m, u = 2 * pp + u2;
            ((ull*)&wrk[m][pp][h])[u2] =
                pack2(w_r1[row * 33 + 1 + 2 * u] * TANH_SC,
                      w_r1[row * 33 + 2 + 2 * u] * TANH_SC);
        }
        if (tid < 32) {
            int h = tid >> 4, m = tid & 15;
            int row = h * 16 + m;
            bw1s[m][h] = pack2(b_r1[row] * TANH_SC, w_r1[row * 33] * TANH_SC);
        }
        if (tid >= 64 && tid < 80) {
            int h = (tid - 64) >> 3, pp = (tid - 64) & 7;
            wr2s[h][pp] = pack2(w_r2[16 * h + 2 * pp], w_r2[16 * h + 2 * pp + 1]);
        }
        if (tid == 80) sc[0] = b_r2[0];
    } else {
        #pragma unroll
        for (int k = 0; k < 2; k++) {
            int idx = tid * 2 + k;
            int u2 = idx & 1, h = (idx >> 1) & 1, pp = (idx >> 2) & 7, m = idx >> 5;
            int row = h * 16 + m, u = 2 * pp + u2;
            ((ull*)&wak[m][pp][h])[u2] =
                pack2(w_a1[row * 36 + 4 + 2 * u] * TANH_SC,
                      w_a1[row * 36 + 5 + 2 * u] * TANH_SC);
        }
        if (tid < 128) {
            int a = tid >> 5, h = (tid >> 4) & 1, m = tid & 15;
            int row = h * 16 + m;
            colbf[a][h][m] = (w_a1[row * 36 + a] + b_a1[row]) * TANH_SC;
        }
        if (tid >= 128 && tid < 192) {
            int k2 = (tid - 128) >> 4, h = (tid - 128 >> 3) & 1, pp = (tid - 128) & 7;
            wa2s[k2][h][pp] = pack2(w_a2[k2 * 32 + 16 * h + 2 * pp],
                                    w_a2[k2 * 32 + 16 * h + 2 * pp + 1]);
        }
        if (tid >= 192 && tid < 196) sc[1 + tid - 192] = b_a2[tid - 192];
    }
    __syncthreads();

    const int lane = tid & 31, wid = tid >> 5;
    const int h  = lane & 1;
    const int el = lane >> 1;
    const int cta_mod = is_reward ? blockIdx.x : blockIdx.x - 64;
    const long long b = (long long)cta_mod * 128 + wid * 16 + el;
    const int*   ap = g_act_t + b;
    const float* rp = g_rew_t + b;

    ull sh[8];
    #pragma unroll
    for (int u = 0; u < 8; u++) sh[u] = 0ull;

    float* op = out + (b * NSTEP) * 4 + 2 * h;   // this lane's 2 output slots

    if (is_reward) {
        ull bi[16];
        #pragma unroll
        for (int m = 0; m < 16; m++) bi[m] = bw1s[m][h];
        ull w2r[8];
        #pragma unroll
        for (int pp = 0; pp < 8; pp++) w2r[pp] = wr2s[h][pp];
        const float br2 = sc[0];
        const int   kA = 2 * h, kB = 2 * h + 1;
        float qA = 0.f, qB = 0.f;

        int   a_cur = ap[0];
        float r_cur = rp[0];
        for (int t = 0; t < NSTEP; t++) {
            const int   a_nxt = ap[(t + 1) * B_SZ];
            const float r_nxt = rp[(t + 1) * B_SZ];
            ull xo[8];
            #pragma unroll
            for (int u = 0; u < 8; u++) xo[u] = shflx64(sh[u], 1);
            const ull rv = pack2(1.0f, r_cur);

            float sn[16];
            #pragma unroll
            for (int m4 = 0; m4 < 4; m4++) {
                ull acc[4];
                #pragma unroll
                for (int mm = 0; mm < 4; mm++)
                    acc[mm] = mul2(bi[m4 * 4 + mm], rv);   // {b', w0'*r}
                #pragma unroll
                for (int ppo = 0; ppo < 4; ppo++) {         // own half first
                    const int pp = h * 4 + ppo;
                    #pragma unroll
                    for (int mm = 0; mm < 4; mm++) {
                        ulonglong2 w = wrk[m4 * 4 + mm][pp][h];
                        ffma2(acc[mm], w.x, sh[2 * ppo]);
                        ffma2(acc[mm], w.y, sh[2 * ppo + 1]);
                    }
                }
                #pragma unroll
                for (int ppo = 0; ppo < 4; ppo++) {         // partner half
                    const int pq = (1 - h) * 4 + ppo;
                    #pragma unroll
                    for (int mm = 0; mm < 4; mm++) {
                        ulonglong2 w = wrk[m4 * 4 + mm][pq][h];
                        ffma2(acc[mm], w.x, xo[2 * ppo]);
                        ffma2(acc[mm], w.y, xo[2 * ppo + 1]);
                    }
                }
                #pragma unroll
                for (int mm = 0; mm < 4; mm++) {
                    float2 u = unpack2(acc[mm]);
                    sn[m4 * 4 + mm] = tanh_pre(u.x + u.y);
                }
            }
            #pragma unroll
            for (int u = 0; u < 8; u++) sh[u] = pack2(sn[2 * u], sn[2 * u + 1]);

            ull qa = 0ull;
            #pragma unroll
            for (int pp = 0; pp < 8; pp++) ffma2(qa, w2r[pp], sh[pp]);
            float2 qf = unpack2(qa);
            float qs = qf.x + qf.y;
            qs += __shfl_xor_sync(0xFFFFFFFFu, qs, 1);
            const float q_new = qs + br2;

            qA = (a_cur == kA) ? q_new : qA * 0.95f;
            qB = (a_cur == kB) ? q_new : qB * 0.95f;
            atomicAdd(op + (size_t)t * 4,     qA);
            atomicAdd(op + (size_t)t * 4 + 1, qB);

            a_cur = a_nxt; r_cur = r_nxt;
        }
    } else {
        ull w2a[4][8];
        #pragma unroll
        for (int k = 0; k < 4; k++)
            #pragma unroll
            for (int pp = 0; pp < 8; pp++) w2a[k][pp] = wa2s[k][h][pp];
        const float baA = h ? sc[3] : sc[1];
        const float baB = h ? sc[4] : sc[2];

        int a_cur = ap[0];
        for (int t = 0; t < NSTEP; t++) {
            const int a_nxt = ap[(t + 1) * B_SZ];
            ull xo[8];
            #pragma unroll
            for (int u = 0; u < 8; u++) xo[u] = shflx64(sh[u], 1);

            float sn[16];
            #pragma unroll
            for (int m4 = 0; m4 < 4; m4++) {
                const float4 cb = *(const float4*)&colbf[a_cur][h][m4 * 4];
                ull acc[4];
                #pragma unroll
                for (int mm = 0; mm < 4; mm++) acc[mm] = 0ull;
                #pragma unroll
                for (int ppo = 0; ppo < 4; ppo++) {
                    const int pp = h * 4 + ppo;
                    #pragma unroll
                    for (int mm = 0; mm < 4; mm++) {
                        ulonglong2 w = wak[m4 * 4 + mm][pp][h];
                        ffma2(acc[mm], w.x, sh[2 * ppo]);
                        ffma2(acc[mm], w.y, sh[2 * ppo + 1]);
                    }
                }
                #pragma unroll
                for (int ppo = 0; ppo < 4; ppo++) {
                    const int pq = (1 - h) * 4 + ppo;
                    #pragma unroll
                    for (int mm = 0; mm < 4; mm++) {
                        ulonglong2 w = wak[m4 * 4 + mm][pq][h];
                        ffma2(acc[mm], w.x, xo[2 * ppo]);
                        ffma2(acc[mm], w.y, xo[2 * ppo + 1]);
                    }
                }
                const float cbv[4] = {cb.x, cb.y, cb.z, cb.w};
                #pragma unroll
                for (int mm = 0; mm < 4; mm++) {
                    float2 u = unpack2(acc[mm]);
                    sn[m4 * 4 + mm] = tanh_pre(u.x + u.y + cbv[mm]);
                }
            }
            #pragma unroll
            for (int u = 0; u < 8; u++) sh[u] = pack2(sn[2 * u], sn[2 * u + 1]);

            ull ca0 = 0ull, ca1 = 0ull, ca2 = 0ull, ca3 = 0ull;
            #pragma unroll
            for (int pp = 0; pp < 8; pp++) {
                ffma2(ca0, w2a[0][pp], sh[pp]);
                ffma2(ca1, w2a[1][pp], sh[pp]);
                ffma2(ca2, w2a[2][pp], sh[pp]);
                ffma2(ca3, w2a[3][pp], sh[pp]);
            }
            float2 f0 = unpack2(ca0), f1 = unpack2(ca1), f2 = unpack2(ca2), f3 = unpack2(ca3);
            ull v01 = pack2(f0.x + f0.y, f1.x + f1.y);
            ull v23 = pack2(f2.x + f2.y, f3.x + f3.y);
            v01 = add2(v01, shflx64(v01, 1));
            v23 = add2(v23, shflx64(v23, 1));
            const ull    vsel = h ? v23 : v01;
            const float2 vv   = unpack2(vsel);
            atomicAdd(op + (size_t)t * 4,     vv.x + baA);
            atomicAdd(op + (size_t)t * 4 + 1, vv.y + baB);

            a_cur = a_nxt;
        }
    }
}

extern "C" void kernel_launch(void* const* d_in, const int* in_sizes, int n_in,
                              void* d_out, int out_size) {
    (void)in_sizes; (void)n_in; (void)out_size;
    transpose_kernel<<<dim3(T_LEN / 32, B_SZ / 32, 3), dim3(32, 8)>>>(
        (const int*)d_in[0], (const float*)d_in[1], (float*)d_out);
    memann_mod<<<128, 256>>>(
        (const float*)d_in[2], (const float*)d_in[3],
        (const float*)d_in[4], (const float*)d_in[5],
        (const float*)d_in[6], (const float*)d_in[7],
        (const float*)d_in[8], (const float*)d_in[9],
        (float*)d_out);
}

// round 11
// speedup vs baseline: 1.8318x; 1.0356x over previous
#include <cuda_runtime.h>

#define T_LEN  1024
#define NSTEP  1023
#define B_SZ   8192

typedef unsigned long long ull;

// scratch: time-major inputs
__device__ int   g_act_t[T_LEN * B_SZ];            // [t][b]
__device__ float g_rew_t[T_LEN * B_SZ];            // [t][b]

// ---------------- packed f32x2 helpers ----------------
__device__ __forceinline__ void ffma2(ull& d, ull a, ull b) {
    asm("fma.rn.f32x2 %0, %1, %2, %0;" : "+l"(d) : "l"(a), "l"(b));
}
__device__ __forceinline__ ull mul2(ull a, ull b) {
    ull r; asm("mul.rn.f32x2 %0, %1, %2;" : "=l"(r) : "l"(a), "l"(b)); return r;
}
__device__ __forceinline__ ull pack2(float x, float y) {
    ull r; asm("mov.b64 %0, {%1, %2};" : "=l"(r) : "f"(x), "f"(y)); return r;
}
__device__ __forceinline__ float2 unpack2(ull v) {
    float2 r; asm("mov.b64 {%0, %1}, %2;" : "=f"(r.x), "=f"(r.y) : "l"(v)); return r;
}
__device__ __forceinline__ ull shflx64(ull v, int m) {
    return __shfl_xor_sync(0xFFFFFFFFu, v, m);
}
// input pre-scaled by 2*log2(e):  tanh = 1 - 2/(2^x' + 1)   (~1e-6 abs err)
__device__ __forceinline__ float tanh_pre(float xs) {
    float e, r;
    asm("ex2.approx.f32 %0, %1;" : "=f"(e) : "f"(xs));
    asm("rcp.approx.f32 %0, %1;" : "=f"(r) : "f"(e + 1.0f));
    return fmaf(-2.0f, r, 1.0f);
}
#define TANH_SC 2.8853900817779268f   // 2*log2(e)

// ---------------- transpose [B][T] -> [T][B]  +  zero(out) ----------------
__global__ void __launch_bounds__(256)
transpose_kernel(const int* __restrict__ act, const float* __restrict__ rew,
                 float* __restrict__ out) {
    const int tx = threadIdx.x, ty = threadIdx.y;
    if (blockIdx.z == 2) {
        const size_t base =
            ((size_t)blockIdx.y * gridDim.x + blockIdx.x) * (size_t)NSTEP;
        float4* o4 = (float4*)out;
        const float4 z = make_float4(0.f, 0.f, 0.f, 0.f);
        const int tid = ty * 32 + tx;
        for (int i = tid; i < NSTEP; i += 256) o4[base + i] = z;
        return;
    }
    __shared__ unsigned tile[32][33];
    const int tt = blockIdx.x * 32, tb = blockIdx.y * 32;
    const unsigned* src = (blockIdx.z == 0) ? (const unsigned*)act : (const unsigned*)rew;
    unsigned*       dst = (blockIdx.z == 0) ? (unsigned*)g_act_t  : (unsigned*)g_rew_t;
    #pragma unroll
    for (int i = 0; i < 32; i += 8)
        tile[ty + i][tx] = src[(long long)(tb + ty + i) * T_LEN + tt + tx];
    __syncthreads();
    #pragma unroll
    for (int i = 0; i < 32; i += 8)
        dst[(long long)(tt + ty + i) * B_SZ + tb + tx] = tile[tx][ty + i];
}

// ---------------- main recurrent kernel ----------------
// R10 geometry (128 CTAs x 256 thr; 2 lanes/element) + pipelined epilogue:
// outputs for step t are computed at the TOP of step t+1, reusing that step's
// xo shuffles, as fully in-lane dots (no epilogue shuffles). Weight rows for
// the second-layer dots are pre-reordered per-lane (own half pairs first).
__global__ void __launch_bounds__(256, 1)
memann_mod(const float* __restrict__ w_r1, const float* __restrict__ b_r1,
           const float* __restrict__ w_r2, const float* __restrict__ b_r2,
           const float* __restrict__ w_a1, const float* __restrict__ b_a1,
           const float* __restrict__ w_a2, const float* __restrict__ b_a2,
           float*       __restrict__ out)
{
    __shared__ __align__(16) ulonglong2 wrk[16][8][2];  // [m][pp][h]: row h*16+m
    __shared__ __align__(16) ulonglong2 wak[16][8][2];
    __shared__ __align__(16) ull  bw1s[16][2];          // {b_r1', w_r1[.,0]'}
    __shared__ __align__(16) ull  wr2n[2][16];          // [h][pp]: own-half-first
    __shared__ __align__(16) ull  wa2n[2][2][16];       // [h][k2][pp]: k=2h+k2
    __shared__ __align__(16) float colbf[4][2][16];     // (w_a1[r][a]+b_a1[r])'
    __shared__ float sc[5];                              // b_r2, b_a2[0..3]

    const int tid = threadIdx.x;
    const bool is_reward = blockIdx.x < 64;

    // ---- staging ----
    if (is_reward) {
        #pragma unroll
        for (int k = 0; k < 2; k++) {
            int idx = tid * 2 + k;                 // 512 ull
            int u2 = idx & 1, h = (idx >> 1) & 1, pp = (idx >> 2) & 7, m = idx >> 5;
            int row = h * 16 + m, u = 2 * pp + u2;
            ((ull*)&wrk[m][pp][h])[u2] =
                pack2(w_r1[row * 33 + 1 + 2 * u] * TANH_SC,
                      w_r1[row * 33 + 2 + 2 * u] * TANH_SC);
        }
        if (tid < 32) {
            int h = tid >> 4, m = tid & 15;
            int row = h * 16 + m;
            bw1s[m][h] = pack2(b_r1[row] * TANH_SC, w_r1[row * 33] * TANH_SC);
        }
        if (tid >= 64 && tid < 96) {               // wr2n: own-half-first layout
            int h = (tid - 64) >> 4, pp = (tid - 64) & 15;
            int d = (pp < 8) ? 16 * h + 2 * pp : 16 * (1 - h) + 2 * (pp - 8);
            wr2n[h][pp] = pack2(w_r2[d], w_r2[d + 1]);
        }
        if (tid == 96) sc[0] = b_r2[0];
    } else {
        #pragma unroll
        for (int k = 0; k < 2; k++) {
            int idx = tid * 2 + k;
            int u2 = idx & 1, h = (idx >> 1) & 1, pp = (idx >> 2) & 7, m = idx >> 5;
            int row = h * 16 + m, u = 2 * pp + u2;
            ((ull*)&wak[m][pp][h])[u2] =
                pack2(w_a1[row * 36 + 4 + 2 * u] * TANH_SC,
                      w_a1[row * 36 + 5 + 2 * u] * TANH_SC);
        }
        if (tid < 128) {
            int a = tid >> 5, h = (tid >> 4) & 1, m = tid & 15;
            int row = h * 16 + m;
            colbf[a][h][m] = (w_a1[row * 36 + a] + b_a1[row]) * TANH_SC;
        }
        if (tid >= 128 && tid < 192) {             // wa2n: rows k=2h+k2, own-first
            int idx = tid - 128;
            int h = idx >> 5, k2 = (idx >> 4) & 1, pp = idx & 15;
            int kk = 2 * h + k2;
            int d = (pp < 8) ? 16 * h + 2 * pp : 16 * (1 - h) + 2 * (pp - 8);
            wa2n[h][k2][pp] = pack2(w_a2[kk * 32 + d], w_a2[kk * 32 + d + 1]);
        }
        if (tid >= 192 && tid < 196) sc[1 + tid - 192] = b_a2[tid - 192];
    }
    __syncthreads();

    const int lane = tid & 31, wid = tid >> 5;
    const int h  = lane & 1;
    const int el = lane >> 1;
    const int cta_mod = is_reward ? blockIdx.x : blockIdx.x - 64;
    const long long b = (long long)cta_mod * 128 + wid * 16 + el;
    const int*   ap = g_act_t + b;
    const float* rp = g_rew_t + b;

    ull sh[8];
    #pragma unroll
    for (int u = 0; u < 8; u++) sh[u] = 0ull;

    float* op = out + (b * NSTEP) * 4 + 2 * h;   // this lane's 2 output slots

    if (is_reward) {
        ull bi[16];
        #pragma unroll
        for (int m = 0; m < 16; m++) bi[m] = bw1s[m][h];
        ull w2f[16];                               // full w_r2, own-half-first
        #pragma unroll
        for (int pp = 0; pp < 16; pp++) w2f[pp] = wr2n[h][pp];
        const float br2 = sc[0];
        const int   kA = 2 * h, kB = 2 * h + 1;
        float qA = 0.f, qB = 0.f;

        int   a_prev = 0;
        int   a_cur  = ap[0];
        float r_cur  = rp[0];
        for (int t = 0; t < NSTEP; t++) {
            const int   a_nxt = ap[(t + 1) * B_SZ];
            const float r_nxt = rp[(t + 1) * B_SZ];
            ull xo[8];
            #pragma unroll
            for (int u = 0; u < 8; u++) xo[u] = shflx64(sh[u], 1);

            // ---- pipelined epilogue: emit output for step t-1 ----
            if (t > 0) {
                ull qa = 0ull;
                #pragma unroll
                for (int pp = 0; pp < 8; pp++) {
                    ffma2(qa, w2f[pp],     sh[pp]);
                    ffma2(qa, w2f[8 + pp], xo[pp]);
                }
                const float2 qf = unpack2(qa);
                const float q_new = qf.x + qf.y + br2;
                qA = (a_prev == kA) ? q_new : qA * 0.95f;
                qB = (a_prev == kB) ? q_new : qB * 0.95f;
                atomicAdd(op + (size_t)(t - 1) * 4,     qA);
                atomicAdd(op + (size_t)(t - 1) * 4 + 1, qB);
            }

            const ull rv = pack2(1.0f, r_cur);
            float sn[16];
            #pragma unroll
            for (int m4 = 0; m4 < 4; m4++) {
                ull acc[4];
                #pragma unroll
                for (int mm = 0; mm < 4; mm++)
                    acc[mm] = mul2(bi[m4 * 4 + mm], rv);   // {b', w0'*r}
                #pragma unroll
                for (int ppo = 0; ppo < 4; ppo++) {         // own half first
                    const int pp = h * 4 + ppo;
                    #pragma unroll
                    for (int mm = 0; mm < 4; mm++) {
                        ulonglong2 w = wrk[m4 * 4 + mm][pp][h];
                        ffma2(acc[mm], w.x, sh[2 * ppo]);
                        ffma2(acc[mm], w.y, sh[2 * ppo + 1]);
                    }
                }
                #pragma unroll
                for (int ppo = 0; ppo < 4; ppo++) {         // partner half
                    const int pq = (1 - h) * 4 + ppo;
                    #pragma unroll
                    for (int mm = 0; mm < 4; mm++) {
                        ulonglong2 w = wrk[m4 * 4 + mm][pq][h];
                        ffma2(acc[mm], w.x, xo[2 * ppo]);
                        ffma2(acc[mm], w.y, xo[2 * ppo + 1]);
                    }
                }
                #pragma unroll
                for (int mm = 0; mm < 4; mm++) {
                    float2 u = unpack2(acc[mm]);
                    sn[m4 * 4 + mm] = tanh_pre(u.x + u.y);
                }
            }
            #pragma unroll
            for (int u = 0; u < 8; u++) sh[u] = pack2(sn[2 * u], sn[2 * u + 1]);

            a_prev = a_cur; a_cur = a_nxt; r_cur = r_nxt;
        }
        // final epilogue for step NSTEP-1
        {
            ull xo[8];
            #pragma unroll
            for (int u = 0; u < 8; u++) xo[u] = shflx64(sh[u], 1);
            ull qa = 0ull;
            #pragma unroll
            for (int pp = 0; pp < 8; pp++) {
                ffma2(qa, w2f[pp],     sh[pp]);
                ffma2(qa, w2f[8 + pp], xo[pp]);
            }
            const float2 qf = unpack2(qa);
            const float q_new = qf.x + qf.y + br2;
            qA = (a_prev == kA) ? q_new : qA * 0.95f;
            qB = (a_prev == kB) ? q_new : qB * 0.95f;
            atomicAdd(op + (size_t)(NSTEP - 1) * 4,     qA);
            atomicAdd(op + (size_t)(NSTEP - 1) * 4 + 1, qB);
        }
    } else {
        ull w2A[16], w2B[16];                      // rows 2h, 2h+1 (own-first)
        #pragma unroll
        for (int pp = 0; pp < 16; pp++) {
            w2A[pp] = wa2n[h][0][pp];
            w2B[pp] = wa2n[h][1][pp];
        }
        const float baA = h ? sc[3] : sc[1];
        const float baB = h ? sc[4] : sc[2];

        int a_cur = ap[0];
        for (int t = 0; t < NSTEP; t++) {
            const int a_nxt = ap[(t + 1) * B_SZ];
            ull xo[8];
            #pragma unroll
            for (int u = 0; u < 8; u++) xo[u] = shflx64(sh[u], 1);

            // ---- pipelined epilogue: emit output for step t-1 ----
            if (t > 0) {
                ull cA = 0ull, cB = 0ull;
                #pragma unroll
                for (int pp = 0; pp < 8; pp++) {
                    ffma2(cA, w2A[pp],     sh[pp]);
                    ffma2(cB, w2B[pp],     sh[pp]);
                    ffma2(cA, w2A[8 + pp], xo[pp]);
                    ffma2(cB, w2B[8 + pp], xo[pp]);
                }
                const float2 fA = unpack2(cA), fB = unpack2(cB);
                atomicAdd(op + (size_t)(t - 1) * 4,     fA.x + fA.y + baA);
                atomicAdd(op + (size_t)(t - 1) * 4 + 1, fB.x + fB.y + baB);
            }

            float sn[16];
            #pragma unroll
            for (int m4 = 0; m4 < 4; m4++) {
                const float4 cb = *(const float4*)&colbf[a_cur][h][m4 * 4];
                ull acc[4];
                #pragma unroll
                for (int mm = 0; mm < 4; mm++) acc[mm] = 0ull;
                #pragma unroll
                for (int ppo = 0; ppo < 4; ppo++) {
                    const int pp = h * 4 + ppo;
                    #pragma unroll
                    for (int mm = 0; mm < 4; mm++) {
                        ulonglong2 w = wak[m4 * 4 + mm][pp][h];
                        ffma2(acc[mm], w.x, sh[2 * ppo]);
                        ffma2(acc[mm], w.y, sh[2 * ppo + 1]);
                    }
                }
                #pragma unroll
                for (int ppo = 0; ppo < 4; ppo++) {
                    const int pq = (1 - h) * 4 + ppo;
                    #pragma unroll
                    for (int mm = 0; mm < 4; mm++) {
                        ulonglong2 w = wak[m4 * 4 + mm][pq][h];
                        ffma2(acc[mm], w.x, xo[2 * ppo]);
                        ffma2(acc[mm], w.y, xo[2 * ppo + 1]);
                    }
                }
                const float cbv[4] = {cb.x, cb.y, cb.z, cb.w};
                #pragma unroll
                for (int mm = 0; mm < 4; mm++) {
                    float2 u = unpack2(acc[mm]);
                    sn[m4 * 4 + mm] = tanh_pre(u.x + u.y + cbv[mm]);
                }
            }
            #pragma unroll
            for (int u = 0; u < 8; u++) sh[u] = pack2(sn[2 * u], sn[2 * u + 1]);

            a_cur = a_nxt;
        }
        // final epilogue for step NSTEP-1
        {
            ull xo[8];
            #pragma unroll
            for (int u = 0; u < 8; u++) xo[u] = shflx64(sh[u], 1);
            ull cA = 0ull, cB = 0ull;
            #pragma unroll
            for (int pp = 0; pp < 8; pp++) {
                ffma2(cA, w2A[pp],     sh[pp]);
                ffma2(cB, w2B[pp],     sh[pp]);
                ffma2(cA, w2A[8 + pp], xo[pp]);
                ffma2(cB, w2B[8 + pp], xo[pp]);
            }
            const float2 fA = unpack2(cA), fB = unpack2(cB);
            atomicAdd(op + (size_t)(NSTEP - 1) * 4,     fA.x + fA.y + baA);
            atomicAdd(op + (size_t)(NSTEP - 1) * 4 + 1, fB.x + fB.y + baB);
        }
    }
}

extern "C" void kernel_launch(void* const* d_in, const int* in_sizes, int n_in,
                              void* d_out, int out_size) {
    (void)in_sizes; (void)n_in; (void)out_size;
    transpose_kernel<<<dim3(T_LEN / 32, B_SZ / 32, 3), dim3(32, 8)>>>(
        (const int*)d_in[0], (const float*)d_in[1], (float*)d_out);
    memann_mod<<<128, 256>>>(
        (const float*)d_in[2], (const float*)d_in[3],
        (const float*)d_in[4], (const float*)d_in[5],
        (const float*)d_in[6], (const float*)d_in[7],
        (const float*)d_in[8], (const float*)d_in[9],
        (float*)d_out);
}